// round 7
// baseline (speedup 1.0000x reference)
#include <cuda_runtime.h>
#include <math.h>

// Problem constants (shapes fixed by the dataset)
#define P_PILLARS 48000
#define NPTS      32
#define NCH       64
#define GX        432
#define GY        496
#define NBLK1     296        // pass1 grid (fixed so every partial slot is written each call)
#define NACC      44         // 8 sums + 36 upper-tri second moments

// Scratch (no allocations allowed): overwritten fully & deterministically every launch.
__device__ float  g_part[NBLK1 * NACC];
__device__ float4 g_Wp[NCH * 2];     // folded 8-dim weights per channel
__device__ float  g_scale[NCH];
__device__ float  g_bias[NCH];

// ---------------------------------------------------------------------------
// Pass 1: feature moments. warp-per-pillar, grid-stride.
// g = mask * [x-cellx, y-celly, z, w, x-mx, y-my, z-mz, 1]
// Accumulate sum(g) (8) and sum(g_i g_j), i<=j (36) -> per-block partials.
// ---------------------------------------------------------------------------
__global__ __launch_bounds__(256) void pass1_kernel(
    const float4* __restrict__ pillars4,
    const int* __restrict__ coors_x,
    const int* __restrict__ coors_y,
    const int* __restrict__ npoints)
{
    const int tid  = threadIdx.x;
    const int lane = tid & 31;
    const int warp = tid >> 5;

    float acc[NACC];
#pragma unroll
    for (int i = 0; i < NACC; i++) acc[i] = 0.f;

    for (int p = blockIdx.x * 8 + warp; p < P_PILLARS; p += NBLK1 * 8) {
        float4 pt = pillars4[p * NPTS + lane];
        float sx = pt.x, sy = pt.y, sz = pt.z;
#pragma unroll
        for (int o = 16; o > 0; o >>= 1) {
            sx += __shfl_xor_sync(0xffffffffu, sx, o);
            sy += __shfl_xor_sync(0xffffffffu, sy, o);
            sz += __shfl_xor_sync(0xffffffffu, sz, o);
        }
        int   npv = npoints[p];
        float npf = (float)npv;
        float mx = sx / npf, my = sy / npf, mz = sz / npf;
        float cxw = (float)coors_x[p] * 0.16f + 0.08f;
        float cyw = (float)coors_y[p] * 0.16f - 39.60f;
        float m = (lane < npv) ? 1.f : 0.f;

        float g[8];
        g[0] = (pt.x - cxw) * m;
        g[1] = (pt.y - cyw) * m;
        g[2] = pt.z * m;
        g[3] = pt.w * m;
        g[4] = (pt.x - mx) * m;
        g[5] = (pt.y - my) * m;
        g[6] = (pt.z - mz) * m;
        g[7] = m;

#pragma unroll
        for (int i = 0; i < 8; i++) acc[i] += g[i];
        {
            int k = 8;
#pragma unroll
            for (int i = 0; i < 8; i++) {
#pragma unroll
                for (int j = i; j < 8; j++) { acc[k] += g[i] * g[j]; k++; }
            }
        }
    }

    // warp reduce
#pragma unroll
    for (int i = 0; i < NACC; i++) {
        float v = acc[i];
#pragma unroll
        for (int o = 16; o > 0; o >>= 1) v += __shfl_xor_sync(0xffffffffu, v, o);
        acc[i] = v;
    }

    __shared__ float sred[8][NACC];
    if (lane == 0) {
#pragma unroll
        for (int i = 0; i < NACC; i++) sred[warp][i] = acc[i];
    }
    __syncthreads();
    if (tid < NACC) {
        float s = 0.f;
#pragma unroll
        for (int w = 0; w < 8; w++) s += sred[w][tid];
        g_part[blockIdx.x * NACC + tid] = s;   // overwrite: no zero-init needed
    }
}

// ---------------------------------------------------------------------------
// Stats: reduce partials (double), derive per-channel scale/bias + folded W'.
// ---------------------------------------------------------------------------
__global__ void stats_kernel(const float* __restrict__ W,
                             const float* __restrict__ gamma,
                             const float* __restrict__ beta)
{
    __shared__ double sm[NACC];
    const int tid = threadIdx.x;
    if (tid < NACC) {
        double s = 0.0;
        for (int b = 0; b < NBLK1; b++) s += (double)g_part[b * NACC + tid];
        sm[tid] = s;
    }
    __syncthreads();
    if (tid < NCH) {
        const float* wr = W + tid * 10;
        double w[8];
        w[0] = (double)wr[0] + (double)wr[7];   // xo appears at feat 0 and 7
        w[1] = (double)wr[1] + (double)wr[8];   // yo appears at feat 1 and 8
        w[2] = (double)wr[2];
        w[3] = (double)wr[3];
        w[4] = (double)wr[4];
        w[5] = (double)wr[5];
        w[6] = (double)wr[6];
        w[7] = -(double)wr[9];                  // zo = -1 * mask

        const double cnt = (double)P_PILLARS * (double)NPTS;
        double mu = 0.0;
        for (int f = 0; f < 8; f++) mu += w[f] * sm[f];
        mu /= cnt;

        double ex2 = 0.0;
        int k = 8;
        for (int i = 0; i < 8; i++)
            for (int j = i; j < 8; j++) {
                double t = w[i] * w[j] * sm[k];
                ex2 += (i == j) ? t : 2.0 * t;
                k++;
            }
        ex2 /= cnt;
        double var = ex2 - mu * mu;

        double sc = (double)gamma[tid] / sqrt(var + 1e-3);
        g_scale[tid] = (float)sc;
        g_bias[tid]  = (float)((double)beta[tid] - mu * sc);
        g_Wp[tid * 2 + 0] = make_float4((float)w[0], (float)w[1], (float)w[2], (float)w[3]);
        g_Wp[tid * 2 + 1] = make_float4((float)w[4], (float)w[5], (float)w[6], (float)w[7]);
    }
}

// ---------------------------------------------------------------------------
// Pass 2: 4 pillars/block, 64 threads/pillar (thread = channel).
// Build g into shared (float4 pairs), dot with W', fused BN+ReLU+max, scatter.
// relu(scale*x+bias) for masked points == relu(bias) automatically (g==0 -> x==0
// and bias is folded so the masked contribution matches reference: feats==0 row
// gives x==0 -> BN -> relu(bias_c); same formula applies).
// ---------------------------------------------------------------------------
__global__ __launch_bounds__(256) void pass2_kernel(
    const float4* __restrict__ pillars4,
    const int* __restrict__ coors_x,
    const int* __restrict__ coors_y,
    const int* __restrict__ coors_b,
    const int* __restrict__ npoints,
    float* __restrict__ out)
{
    __shared__ float4 shg[4 * NPTS * 2];   // [pillar][point][2 x float4] = 4 KB
    const int tid = threadIdx.x;
    const int lp  = tid >> 6;                       // local pillar 0..3
    const int pid = blockIdx.x * 4 + lp;

    if ((tid & 32) == 0) {                          // even warps: one full warp per pillar
        const int n = tid & 31;
        float4 pt = pillars4[pid * NPTS + n];
        float sx = pt.x, sy = pt.y, sz = pt.z;
#pragma unroll
        for (int o = 16; o > 0; o >>= 1) {
            sx += __shfl_xor_sync(0xffffffffu, sx, o);
            sy += __shfl_xor_sync(0xffffffffu, sy, o);
            sz += __shfl_xor_sync(0xffffffffu, sz, o);
        }
        int   npv = npoints[pid];
        float npf = (float)npv;
        float mx = sx / npf, my = sy / npf, mz = sz / npf;
        float cxw = (float)coors_x[pid] * 0.16f + 0.08f;
        float cyw = (float)coors_y[pid] * 0.16f - 39.60f;
        float m = (n < npv) ? 1.f : 0.f;
        shg[(lp * NPTS + n) * 2 + 0] =
            make_float4((pt.x - cxw) * m, (pt.y - cyw) * m, pt.z * m, pt.w * m);
        shg[(lp * NPTS + n) * 2 + 1] =
            make_float4((pt.x - mx) * m, (pt.y - my) * m, (pt.z - mz) * m, m);
    }
    __syncthreads();

    const int c = tid & 63;
    const float4 w0 = g_Wp[c * 2 + 0];
    const float4 w1 = g_Wp[c * 2 + 1];
    const float scale = g_scale[c];
    const float bias  = g_bias[c];

    float mmax = 0.f;                               // all relu outputs >= 0
    const float4* gp = &shg[lp * NPTS * 2];
#pragma unroll
    for (int n = 0; n < NPTS; n++) {
        float4 a  = gp[2 * n];
        float4 bb = gp[2 * n + 1];
        float x = a.x * w0.x + a.y * w0.y + a.z * w0.z + a.w * w0.w
                + bb.x * w1.x + bb.y * w1.y + bb.z * w1.z + bb.w * w1.w;
        mmax = fmaxf(mmax, fmaxf(fmaf(scale, x, bias), 0.f));
    }

    const int b_ = coors_b[pid];
    const int xi = coors_x[pid];
    const int yi = coors_y[pid];
    out[((b_ * NCH + c) * GY + yi) * GX + xi] = mmax;
}

// ---------------------------------------------------------------------------
extern "C" void kernel_launch(void* const* d_in, const int* in_sizes, int n_in,
                              void* d_out, int out_size)
{
    // NOTE: JAX without x64 silently downcasts int64 -> int32; all coordinate
    // arrays are int32 (in_sizes confirms 48000 elements each).
    const float4* pillars4 = (const float4*)d_in[0];  // [48000,32,4] f32
    const float*  W        = (const float*)d_in[1];   // [64,10] f32
    const float*  gamma    = (const float*)d_in[2];   // [64] f32
    const float*  beta     = (const float*)d_in[3];   // [64] f32
    const int*    cx       = (const int*)d_in[4];     // [48000] i32
    const int*    cy       = (const int*)d_in[5];     // [48000] i32
    const int*    cb       = (const int*)d_in[6];     // [48000] i32
    const int*    np       = (const int*)d_in[7];     // [48000] i32
    float*        out      = (float*)d_out;           // [4,64,496,432] f32

    // dense grid is zero except scattered pillar cells (output poisoned -> must clear)
    cudaMemsetAsync(d_out, 0, (size_t)out_size * sizeof(float), 0);

    pass1_kernel<<<NBLK1, 256>>>(pillars4, cx, cy, np);
    stats_kernel<<<1, 64>>>(W, gamma, beta);
    pass2_kernel<<<P_PILLARS / 4, 256>>>(pillars4, cx, cy, cb, np, out);
}

// round 9
// speedup vs baseline: 1.0237x; 1.0237x over previous
#include <cuda_runtime.h>
#include <math.h>

// Problem constants (shapes fixed by the dataset)
#define P_PILLARS 48000
#define NPTS      32
#define NCH       64
#define GX        432
#define GY        496
#define NBLK1     1184       // pass1 grid: 8 blocks/SM on 148 SMs
#define NACC      36         // 8 first moments + 28 second moments among feats 0..6
#define NCELLS    (4 * GY * GX)   // 857088

// Scratch (no allocations allowed): overwritten fully & deterministically every call.
__device__ float  g_part[NBLK1 * NACC];
__device__ float4 g_Wp[NCH * 2];        // folded 8-dim weights per channel
__device__ float  g_scale[NCH];
__device__ float  g_bias[NCH];
__device__ float  g_xmax[P_PILLARS * NCH];   // compact per-pillar output (12.3 MB)
__device__ int    g_cellmap[NCELLS];         // (b,y,x) -> pillar id, -1 = empty (3.4 MB)

// ---------------------------------------------------------------------------
// Pass 1: feature moments (warp-per-pillar, grid-stride) + cellmap clear.
// g = mask * [x-cellx, y-celly, z, w, x-mx, y-my, z-mz, 1]
// Since every g_i (i<7) carries the mask factor and m^2 = m:
//   sum(g_i * g_7) = sum(g_i)   and   sum(g_7^2) = sum(g_7)
// so only 8 first moments + 28 pair moments among feats 0..6 are independent.
// ---------------------------------------------------------------------------
__global__ __launch_bounds__(256) void pass1_kernel(
    const float4* __restrict__ pillars4,
    const int* __restrict__ coors_x,
    const int* __restrict__ coors_y,
    const int* __restrict__ npoints)
{
    const int tid  = threadIdx.x;
    const int lane = tid & 31;
    const int warp = tid >> 5;

    // clear cellmap to -1 (int4 grid-stride); map is consumed only by pass2/paint,
    // which run after this kernel completes (stream order).
    {
        int4 neg1 = make_int4(-1, -1, -1, -1);
        int4* cm4 = (int4*)g_cellmap;
        const int nq = NCELLS / 4;   // 214272
        for (int i = blockIdx.x * 256 + tid; i < nq; i += NBLK1 * 256)
            cm4[i] = neg1;
    }

    float acc[NACC];
#pragma unroll
    for (int i = 0; i < NACC; i++) acc[i] = 0.f;

    for (int p = blockIdx.x * 8 + warp; p < P_PILLARS; p += NBLK1 * 8) {
        float4 pt = pillars4[p * NPTS + lane];
        float sx = pt.x, sy = pt.y, sz = pt.z;
#pragma unroll
        for (int o = 16; o > 0; o >>= 1) {
            sx += __shfl_xor_sync(0xffffffffu, sx, o);
            sy += __shfl_xor_sync(0xffffffffu, sy, o);
            sz += __shfl_xor_sync(0xffffffffu, sz, o);
        }
        int   npv = npoints[p];
        float npf = (float)npv;
        float mx = sx / npf, my = sy / npf, mz = sz / npf;
        float cxw = (float)coors_x[p] * 0.16f + 0.08f;
        float cyw = (float)coors_y[p] * 0.16f - 39.60f;
        float m = (lane < npv) ? 1.f : 0.f;

        float g[8];
        g[0] = (pt.x - cxw) * m;
        g[1] = (pt.y - cyw) * m;
        g[2] = pt.z * m;
        g[3] = pt.w * m;
        g[4] = (pt.x - mx) * m;
        g[5] = (pt.y - my) * m;
        g[6] = (pt.z - mz) * m;
        g[7] = m;

#pragma unroll
        for (int i = 0; i < 8; i++) acc[i] += g[i];
        {
            int k = 8;
#pragma unroll
            for (int i = 0; i < 7; i++) {
#pragma unroll
                for (int j = i; j < 7; j++) { acc[k] += g[i] * g[j]; k++; }
            }
        }
    }

    // warp reduce
#pragma unroll
    for (int i = 0; i < NACC; i++) {
        float v = acc[i];
#pragma unroll
        for (int o = 16; o > 0; o >>= 1) v += __shfl_xor_sync(0xffffffffu, v, o);
        acc[i] = v;
    }

    __shared__ float sred[8][NACC];
    if (lane == 0) {
#pragma unroll
        for (int i = 0; i < NACC; i++) sred[warp][i] = acc[i];
    }
    __syncthreads();
    if (tid < NACC) {
        float s = 0.f;
#pragma unroll
        for (int w = 0; w < 8; w++) s += sred[w][tid];
        g_part[blockIdx.x * NACC + tid] = s;   // overwritten every call
    }
}

// ---------------------------------------------------------------------------
// Stats: reduce partials (double, warp-per-accumulator), derive per-channel
// BN scale/bias and folded 8-dim weights.
// ---------------------------------------------------------------------------
__global__ __launch_bounds__(1024) void stats_kernel(
    const float* __restrict__ W,
    const float* __restrict__ gamma,
    const float* __restrict__ beta)
{
    __shared__ double sm[NACC];
    const int tid  = threadIdx.x;
    const int warp = tid >> 5;
    const int lane = tid & 31;

    for (int a = warp; a < NACC; a += 32) {
        double sd = 0.0;
        for (int b = lane; b < NBLK1; b += 32)
            sd += (double)g_part[b * NACC + a];
#pragma unroll
        for (int o = 16; o > 0; o >>= 1)
            sd += __shfl_xor_sync(0xffffffffu, sd, o);
        if (lane == 0) sm[a] = sd;
    }
    __syncthreads();

    if (tid < NCH) {
        const float* wr = W + tid * 10;
        double w[8];
        w[0] = (double)wr[0] + (double)wr[7];   // xo at feats 0 and 7
        w[1] = (double)wr[1] + (double)wr[8];   // yo at feats 1 and 8
        w[2] = (double)wr[2];
        w[3] = (double)wr[3];
        w[4] = (double)wr[4];
        w[5] = (double)wr[5];
        w[6] = (double)wr[6];
        w[7] = -(double)wr[9];                  // zo = -1 * mask

        const double cnt = (double)P_PILLARS * (double)NPTS;
        double mu = 0.0;
        for (int f = 0; f < 8; f++) mu += w[f] * sm[f];
        mu /= cnt;

        double ex2 = 0.0;
        int k = 8;
        for (int i = 0; i < 7; i++)
            for (int j = i; j < 7; j++) {
                double t = w[i] * w[j] * sm[k];
                ex2 += (i == j) ? t : 2.0 * t;
                k++;
            }
        for (int i = 0; i < 7; i++)             // S(i,7) = sm[i]
            ex2 += 2.0 * w[i] * w[7] * sm[i];
        ex2 += w[7] * w[7] * sm[7];             // S(7,7) = sm[7]
        ex2 /= cnt;
        double var = ex2 - mu * mu;

        double sc = (double)gamma[tid] / sqrt(var + 1e-3);
        g_scale[tid] = (float)sc;
        g_bias[tid]  = (float)((double)beta[tid] - mu * sc);
        g_Wp[tid * 2 + 0] = make_float4((float)w[0], (float)w[1], (float)w[2], (float)w[3]);
        g_Wp[tid * 2 + 1] = make_float4((float)w[4], (float)w[5], (float)w[6], (float)w[7]);
    }
}

// ---------------------------------------------------------------------------
// Pass 2: 4 pillars/block, 64 threads/pillar (thread = channel).
// Build g in shared, dot with W', fused BN+ReLU+max -> compact g_xmax,
// and scatter pillar id into g_cellmap (4B per pillar instead of 256B).
// Masked points give g==0 -> x==0 -> relu(bias): matches reference exactly.
// ---------------------------------------------------------------------------
__global__ __launch_bounds__(256) void pass2_kernel(
    const float4* __restrict__ pillars4,
    const int* __restrict__ coors_x,
    const int* __restrict__ coors_y,
    const int* __restrict__ coors_b,
    const int* __restrict__ npoints)
{
    __shared__ float4 shg[4 * NPTS * 2];   // 4 KB
    const int tid = threadIdx.x;
    const int lp  = tid >> 6;              // local pillar 0..3
    const int pid = blockIdx.x * 4 + lp;

    if ((tid & 32) == 0) {                 // even warps: one warp per pillar
        const int n = tid & 31;
        float4 pt = pillars4[pid * NPTS + n];
        float sx = pt.x, sy = pt.y, sz = pt.z;
#pragma unroll
        for (int o = 16; o > 0; o >>= 1) {
            sx += __shfl_xor_sync(0xffffffffu, sx, o);
            sy += __shfl_xor_sync(0xffffffffu, sy, o);
            sz += __shfl_xor_sync(0xffffffffu, sz, o);
        }
        int   npv = npoints[pid];
        float npf = (float)npv;
        float mx = sx / npf, my = sy / npf, mz = sz / npf;
        int   xi = coors_x[pid];
        int   yi = coors_y[pid];
        float cxw = (float)xi * 0.16f + 0.08f;
        float cyw = (float)yi * 0.16f - 39.60f;
        float m = (n < npv) ? 1.f : 0.f;
        shg[(lp * NPTS + n) * 2 + 0] =
            make_float4((pt.x - cxw) * m, (pt.y - cyw) * m, pt.z * m, pt.w * m);
        shg[(lp * NPTS + n) * 2 + 1] =
            make_float4((pt.x - mx) * m, (pt.y - my) * m, (pt.z - mz) * m, m);
        if (n == 0) {
            int b_ = coors_b[pid];
            g_cellmap[(b_ * GY + yi) * GX + xi] = pid;   // unique cells per batch
        }
    }
    __syncthreads();

    const int c = tid & 63;
    const float4 w0 = g_Wp[c * 2 + 0];
    const float4 w1 = g_Wp[c * 2 + 1];
    const float scale = g_scale[c];
    const float bias  = g_bias[c];

    float mmax = 0.f;                      // all relu outputs >= 0
    const float4* gp = &shg[lp * NPTS * 2];
#pragma unroll
    for (int n = 0; n < NPTS; n++) {
        float4 a  = gp[2 * n];
        float4 bb = gp[2 * n + 1];
        float x = a.x * w0.x + a.y * w0.y + a.z * w0.z + a.w * w0.w
                + bb.x * w1.x + bb.y * w1.y + bb.z * w1.z + bb.w * w1.w;
        mmax = fmaxf(mmax, fmaxf(fmaf(scale, x, bias), 0.f));
    }

    g_xmax[pid * NCH + c] = mmax;          // coalesced 256B per pillar
}

// ---------------------------------------------------------------------------
// Paint: write the whole [4,64,496,432] output once, coalesced float4.
// Block per (b,y): stage the 432-entry cell map row in shared, then stream
// all 64 channel rows; occupied cells gather from the L2-resident g_xmax.
// ---------------------------------------------------------------------------
__global__ __launch_bounds__(256) void paint_kernel(float* __restrict__ out)
{
    __shared__ int smap[GX];
    const int b = blockIdx.x / GY;
    const int y = blockIdx.x % GY;

    const int* mrow = g_cellmap + (b * GY + y) * GX;
    for (int x = threadIdx.x; x < GX; x += 256) smap[x] = mrow[x];
    __syncthreads();

    const size_t plane = (size_t)GY * GX;
    float* obase = out + (size_t)b * NCH * plane + (size_t)y * GX;

    const int NQ = GX / 4;                 // 108 float4 per row
#pragma unroll 4
    for (int i = threadIdx.x; i < NCH * NQ; i += 256) {
        int c  = i / NQ;
        int xq = i - c * NQ;
        int x0 = xq * 4;
        int p0 = smap[x0 + 0], p1 = smap[x0 + 1];
        int p2 = smap[x0 + 2], p3 = smap[x0 + 3];
        float4 v;
        v.x = (p0 < 0) ? 0.f : __ldg(&g_xmax[p0 * NCH + c]);
        v.y = (p1 < 0) ? 0.f : __ldg(&g_xmax[p1 * NCH + c]);
        v.z = (p2 < 0) ? 0.f : __ldg(&g_xmax[p2 * NCH + c]);
        v.w = (p3 < 0) ? 0.f : __ldg(&g_xmax[p3 * NCH + c]);
        ((float4*)(obase + (size_t)c * plane))[xq] = v;
    }
}

// ---------------------------------------------------------------------------
extern "C" void kernel_launch(void* const* d_in, const int* in_sizes, int n_in,
                              void* d_out, int out_size)
{
    // JAX without x64 silently downcasts int64 -> int32: coords are int32.
    const float4* pillars4 = (const float4*)d_in[0];  // [48000,32,4] f32
    const float*  W        = (const float*)d_in[1];   // [64,10] f32
    const float*  gamma    = (const float*)d_in[2];   // [64] f32
    const float*  beta     = (const float*)d_in[3];   // [64] f32
    const int*    cx       = (const int*)d_in[4];     // [48000] i32
    const int*    cy       = (const int*)d_in[5];     // [48000] i32
    const int*    cb       = (const int*)d_in[6];     // [48000] i32
    const int*    np       = (const int*)d_in[7];     // [48000] i32
    float*        out      = (float*)d_out;           // [4,64,496,432] f32

    pass1_kernel<<<NBLK1, 256>>>(pillars4, cx, cy, np);        // moments + map clear
    stats_kernel<<<1, 1024>>>(W, gamma, beta);                 // BN params + folded W
    pass2_kernel<<<P_PILLARS / 4, 256>>>(pillars4, cx, cy, cb, np);  // xmax + map scatter
    paint_kernel<<<4 * GY, 256>>>(out);                        // single full-output write
}

// round 10
// speedup vs baseline: 1.2744x; 1.2448x over previous
#include <cuda_runtime.h>
#include <math.h>

// Problem constants (fixed shapes)
#define P_PILLARS 48000
#define NPTS      32
#define NCH       64
#define GX        432
#define GY        496
#define NBLK1     1184            // pass1 grid
#define NACC      36              // 8 first moments + 28 pair moments (feats 0..6)
#define NCELLS    (4 * GY * GX)   // 857088
#define PPB2      16              // pillars per block in pass2
#define PSTRIDE   65              // padded pillar stride in float4 (bank-conflict free)

// Scratch (no allocations): overwritten fully & deterministically every call.
__device__ float  g_part[NACC * NBLK1];          // transposed: [acc][block]
__device__ float2 g_Wt[8][NCH / 2];              // scale-folded W', transposed [feat][ch]
__device__ __align__(16) float g_bias[NCH];
__device__ float  g_xmax[P_PILLARS * NCH];       // compact per-pillar output (12.3 MB)
__device__ int    g_cellmap[NCELLS];             // (b,y,x) -> pillar id, -1 empty

// ---- f32x2 packed-FMA helpers (FFMA2: only reachable via PTX) -------------
__device__ __forceinline__ unsigned long long pk2(float v) {
    unsigned long long r;
    asm("mov.b64 %0, {%1, %1};" : "=l"(r) : "f"(v));
    return r;
}
__device__ __forceinline__ unsigned long long f2mul(unsigned long long a, unsigned long long b) {
    unsigned long long d;
    asm("mul.rn.f32x2 %0, %1, %2;" : "=l"(d) : "l"(a), "l"(b));
    return d;
}
__device__ __forceinline__ unsigned long long f2fma(unsigned long long a, unsigned long long b,
                                                    unsigned long long c) {
    unsigned long long d;
    asm("fma.rn.f32x2 %0, %1, %2, %3;" : "=l"(d) : "l"(a), "l"(b), "l"(c));
    return d;
}
__device__ __forceinline__ void upk2(unsigned long long v, float& lo, float& hi) {
    asm("mov.b64 {%0, %1}, %2;" : "=f"(lo), "=f"(hi) : "l"(v));
}

// ---------------------------------------------------------------------------
// Pass 1: feature moments (warp-per-pillar, grid-stride) + cellmap clear.
// g = mask * [x-cellx, y-celly, z, w, x-mx, y-my, z-mz, 1];  m^2 = m collapses
// all moments involving g7 to first moments -> 36 independent accumulators.
// ---------------------------------------------------------------------------
__global__ __launch_bounds__(256) void pass1_kernel(
    const float4* __restrict__ pillars4,
    const int* __restrict__ coors_x,
    const int* __restrict__ coors_y,
    const int* __restrict__ npoints)
{
    const int tid  = threadIdx.x;
    const int lane = tid & 31;
    const int warp = tid >> 5;

    {   // clear cellmap (consumed only by later kernels; stream-ordered)
        int4 neg1 = make_int4(-1, -1, -1, -1);
        int4* cm4 = (int4*)g_cellmap;
        const int nq = NCELLS / 4;
        for (int i = blockIdx.x * 256 + tid; i < nq; i += NBLK1 * 256)
            cm4[i] = neg1;
    }

    float acc[NACC];
#pragma unroll
    for (int i = 0; i < NACC; i++) acc[i] = 0.f;

    for (int p = blockIdx.x * 8 + warp; p < P_PILLARS; p += NBLK1 * 8) {
        float4 pt = pillars4[p * NPTS + lane];
        float sx = pt.x, sy = pt.y, sz = pt.z;
#pragma unroll
        for (int o = 16; o > 0; o >>= 1) {
            sx += __shfl_xor_sync(0xffffffffu, sx, o);
            sy += __shfl_xor_sync(0xffffffffu, sy, o);
            sz += __shfl_xor_sync(0xffffffffu, sz, o);
        }
        int   npv = npoints[p];
        float npf = (float)npv;
        float mx = sx / npf, my = sy / npf, mz = sz / npf;
        float cxw = (float)coors_x[p] * 0.16f + 0.08f;
        float cyw = (float)coors_y[p] * 0.16f - 39.60f;
        float m = (lane < npv) ? 1.f : 0.f;

        float g[8];
        g[0] = (pt.x - cxw) * m;
        g[1] = (pt.y - cyw) * m;
        g[2] = pt.z * m;
        g[3] = pt.w * m;
        g[4] = (pt.x - mx) * m;
        g[5] = (pt.y - my) * m;
        g[6] = (pt.z - mz) * m;
        g[7] = m;

#pragma unroll
        for (int i = 0; i < 8; i++) acc[i] += g[i];
        {
            int k = 8;
#pragma unroll
            for (int i = 0; i < 7; i++)
#pragma unroll
                for (int j = i; j < 7; j++) { acc[k] += g[i] * g[j]; k++; }
        }
    }

#pragma unroll
    for (int i = 0; i < NACC; i++) {
        float v = acc[i];
#pragma unroll
        for (int o = 16; o > 0; o >>= 1) v += __shfl_xor_sync(0xffffffffu, v, o);
        acc[i] = v;
    }

    __shared__ float sred[8][NACC];
    if (lane == 0) {
#pragma unroll
        for (int i = 0; i < NACC; i++) sred[warp][i] = acc[i];
    }
    __syncthreads();
    if (tid < NACC) {
        float s = 0.f;
#pragma unroll
        for (int w = 0; w < 8; w++) s += sred[w][tid];
        g_part[tid * NBLK1 + blockIdx.x] = s;   // transposed: stats reads coalesced
    }
}

// ---------------------------------------------------------------------------
// Stats: reduce partials (double, coalesced), derive BN params; write
// scale-FOLDED transposed weights g_Wt[f][c] = scale_c * w'_fc and bias.
// ---------------------------------------------------------------------------
__global__ __launch_bounds__(1024) void stats_kernel(
    const float* __restrict__ W,
    const float* __restrict__ gamma,
    const float* __restrict__ beta)
{
    __shared__ double sm[NACC];
    const int tid  = threadIdx.x;
    const int warp = tid >> 5;
    const int lane = tid & 31;

    for (int a = warp; a < NACC; a += 32) {
        double sd = 0.0;
        const float* row = g_part + a * NBLK1;
        for (int b = lane; b < NBLK1; b += 32) sd += (double)row[b];
#pragma unroll
        for (int o = 16; o > 0; o >>= 1) sd += __shfl_xor_sync(0xffffffffu, sd, o);
        if (lane == 0) sm[a] = sd;
    }
    __syncthreads();

    if (tid < NCH) {
        const float* wr = W + tid * 10;
        double w[8];
        w[0] = (double)wr[0] + (double)wr[7];
        w[1] = (double)wr[1] + (double)wr[8];
        w[2] = (double)wr[2];
        w[3] = (double)wr[3];
        w[4] = (double)wr[4];
        w[5] = (double)wr[5];
        w[6] = (double)wr[6];
        w[7] = -(double)wr[9];

        const double cnt = (double)P_PILLARS * (double)NPTS;
        double mu = 0.0;
        for (int f = 0; f < 8; f++) mu += w[f] * sm[f];
        mu /= cnt;

        double ex2 = 0.0;
        int k = 8;
        for (int i = 0; i < 7; i++)
            for (int j = i; j < 7; j++) {
                double t = w[i] * w[j] * sm[k];
                ex2 += (i == j) ? t : 2.0 * t;
                k++;
            }
        for (int i = 0; i < 7; i++) ex2 += 2.0 * w[i] * w[7] * sm[i];  // S(i,7)=sm[i]
        ex2 += w[7] * w[7] * sm[7];                                    // S(7,7)=sm[7]
        ex2 /= cnt;
        double var = ex2 - mu * mu;

        double sc = (double)gamma[tid] / sqrt(var + 1e-3);
        g_bias[tid] = (float)((double)beta[tid] - mu * sc);
        for (int f = 0; f < 8; f++)
            ((float*)&g_Wt[f][0])[tid] = (float)(sc * w[f]);   // scale folded in
    }
}

// ---------------------------------------------------------------------------
// Pass 2: 16 pillars/block, 16 threads/pillar, 4 channels/thread via f32x2.
// relu & max commute: out_c = relu(max_n(dot_n,c) + bias_c); masked points
// contribute dot = 0 automatically (g == 0).
// ---------------------------------------------------------------------------
__global__ __launch_bounds__(256) void pass2_kernel(
    const float4* __restrict__ pillars4,
    const int* __restrict__ coors_x,
    const int* __restrict__ coors_y,
    const int* __restrict__ coors_b,
    const int* __restrict__ npoints)
{
    __shared__ float4 shg[PPB2 * PSTRIDE];          // padded: 16.6 KB
    const int tid  = threadIdx.x;
    const int lane = tid & 31;
    const int warp = tid >> 5;
    const int pbase = blockIdx.x * PPB2;

    // ---- load phase: each warp builds 2 pillars' g rows ----
#pragma unroll
    for (int r = 0; r < 2; r++) {
        const int lp  = warp * 2 + r;
        const int pid = pbase + lp;
        float4 pt = pillars4[pid * NPTS + lane];
        float sx = pt.x, sy = pt.y, sz = pt.z;
#pragma unroll
        for (int o = 16; o > 0; o >>= 1) {
            sx += __shfl_xor_sync(0xffffffffu, sx, o);
            sy += __shfl_xor_sync(0xffffffffu, sy, o);
            sz += __shfl_xor_sync(0xffffffffu, sz, o);
        }
        int   npv = npoints[pid];
        float npf = (float)npv;
        float mx = sx / npf, my = sy / npf, mz = sz / npf;
        int   xi = coors_x[pid];
        int   yi = coors_y[pid];
        float cxw = (float)xi * 0.16f + 0.08f;
        float cyw = (float)yi * 0.16f - 39.60f;
        float m = (lane < npv) ? 1.f : 0.f;
        shg[lp * PSTRIDE + lane * 2 + 0] =
            make_float4((pt.x - cxw) * m, (pt.y - cyw) * m, pt.z * m, pt.w * m);
        shg[lp * PSTRIDE + lane * 2 + 1] =
            make_float4((pt.x - mx) * m, (pt.y - my) * m, (pt.z - mz) * m, m);
        if (lane == 0) {
            int b_ = coors_b[pid];
            g_cellmap[(b_ * GY + yi) * GX + xi] = pid;
        }
    }
    __syncthreads();

    // ---- compute phase ----
    const int lp = tid >> 4;                // local pillar 0..15
    const int q  = tid & 15;                // channel quad: channels 4q..4q+3
    const int pid = pbase + lp;

    unsigned long long w01[8], w23[8];      // packed (w_c0,w_c1) / (w_c2,w_c3) per feature
#pragma unroll
    for (int f = 0; f < 8; f++) {
        w01[f] = *reinterpret_cast<const unsigned long long*>(&g_Wt[f][2 * q + 0]);
        w23[f] = *reinterpret_cast<const unsigned long long*>(&g_Wt[f][2 * q + 1]);
    }

    float m0 = -3.4e38f, m1 = -3.4e38f, m2 = -3.4e38f, m3 = -3.4e38f;
    const float4* gp = &shg[lp * PSTRIDE];
#pragma unroll 4
    for (int n = 0; n < NPTS; n++) {
        float4 a  = gp[2 * n];
        float4 b4 = gp[2 * n + 1];
        unsigned long long ga0 = pk2(a.x),  ga1 = pk2(a.y),  ga2 = pk2(a.z),  ga3 = pk2(a.w);
        unsigned long long ga4 = pk2(b4.x), ga5 = pk2(b4.y), ga6 = pk2(b4.z), ga7 = pk2(b4.w);

        unsigned long long acc01 = f2mul(ga0, w01[0]);
        unsigned long long acc23 = f2mul(ga0, w23[0]);
        acc01 = f2fma(ga1, w01[1], acc01); acc23 = f2fma(ga1, w23[1], acc23);
        acc01 = f2fma(ga2, w01[2], acc01); acc23 = f2fma(ga2, w23[2], acc23);
        acc01 = f2fma(ga3, w01[3], acc01); acc23 = f2fma(ga3, w23[3], acc23);
        acc01 = f2fma(ga4, w01[4], acc01); acc23 = f2fma(ga4, w23[4], acc23);
        acc01 = f2fma(ga5, w01[5], acc01); acc23 = f2fma(ga5, w23[5], acc23);
        acc01 = f2fma(ga6, w01[6], acc01); acc23 = f2fma(ga6, w23[6], acc23);
        acc01 = f2fma(ga7, w01[7], acc01); acc23 = f2fma(ga7, w23[7], acc23);

        float x0, x1, x2, x3;
        upk2(acc01, x0, x1);
        upk2(acc23, x2, x3);
        m0 = fmaxf(m0, x0); m1 = fmaxf(m1, x1);
        m2 = fmaxf(m2, x2); m3 = fmaxf(m3, x3);
    }

    float4 bv = ((const float4*)g_bias)[q];
    float4 o;
    o.x = fmaxf(m0 + bv.x, 0.f);
    o.y = fmaxf(m1 + bv.y, 0.f);
    o.z = fmaxf(m2 + bv.z, 0.f);
    o.w = fmaxf(m3 + bv.w, 0.f);
    ((float4*)(g_xmax + pid * NCH))[q] = o;       // 256B coalesced per pillar
}

// ---------------------------------------------------------------------------
// Paint: write the full [4,64,496,432] output once, coalesced float4.
// Block per (b,y): int4 map row staged in shared; each thread preloads its 4
// int4 map entries and reuses them across all 8 of its warp's channels.
// ---------------------------------------------------------------------------
__global__ __launch_bounds__(256) void paint_kernel(float* __restrict__ out)
{
    __shared__ int4 smap4[GX / 4];                    // 108 int4
    const int b = blockIdx.x / GY;
    const int y = blockIdx.x % GY;
    const int tid  = threadIdx.x;
    const int lane = tid & 31;
    const int warp = tid >> 5;

    const int4* mrow = (const int4*)(g_cellmap + (b * GY + y) * GX);
    if (tid < GX / 4) smap4[tid] = mrow[tid];
    __syncthreads();

    int4 mp[4];
#pragma unroll
    for (int t = 0; t < 4; t++) {
        int j = lane + 32 * t;
        mp[t] = (j < GX / 4) ? smap4[j] : make_int4(-1, -1, -1, -1);
    }

    const int plane = GY * GX;                        // 214272 (fits int)
    int ro = ((b * NCH + warp * 8) * GY + y) * GX;    // 32-bit indexing throughout
#pragma unroll
    for (int k = 0; k < 8; k++) {
        const int c = warp * 8 + k;
        float4* orow4 = (float4*)(out + ro);
#pragma unroll
        for (int t = 0; t < 4; t++) {
            int j = lane + 32 * t;
            if (j < GX / 4) {
                int4 m = mp[t];
                float4 v;
                v.x = (m.x < 0) ? 0.f : __ldg(&g_xmax[m.x * NCH + c]);
                v.y = (m.y < 0) ? 0.f : __ldg(&g_xmax[m.y * NCH + c]);
                v.z = (m.z < 0) ? 0.f : __ldg(&g_xmax[m.z * NCH + c]);
                v.w = (m.w < 0) ? 0.f : __ldg(&g_xmax[m.w * NCH + c]);
                orow4[j] = v;
            }
        }
        ro += plane;
    }
}

// ---------------------------------------------------------------------------
extern "C" void kernel_launch(void* const* d_in, const int* in_sizes, int n_in,
                              void* d_out, int out_size)
{
    // JAX without x64 silently downcasts int64 -> int32: coords are int32.
    const float4* pillars4 = (const float4*)d_in[0];  // [48000,32,4] f32
    const float*  W        = (const float*)d_in[1];   // [64,10] f32
    const float*  gamma    = (const float*)d_in[2];   // [64] f32
    const float*  beta     = (const float*)d_in[3];   // [64] f32
    const int*    cx       = (const int*)d_in[4];
    const int*    cy       = (const int*)d_in[5];
    const int*    cb       = (const int*)d_in[6];
    const int*    np       = (const int*)d_in[7];
    float*        out      = (float*)d_out;           // [4,64,496,432] f32

    pass1_kernel<<<NBLK1, 256>>>(pillars4, cx, cy, np);
    stats_kernel<<<1, 1024>>>(W, gamma, beta);
    pass2_kernel<<<P_PILLARS / PPB2, 256>>>(pillars4, cx, cy, cb, np);
    paint_kernel<<<4 * GY, 256>>>(out);
}